// round 8
// baseline (speedup 1.0000x reference)
#include <cuda_runtime.h>
#include <cuda_bf16.h>
#include <cstdint>

// Shapes fixed by dataset: B=16384, D=256, C=2000.
// loss = sum_{b, c != label[b]} max(1 + (pred@sig)[b,c] - gt[b], 0)
// gt[b] = dot(pred[b,:], sig[:,label[b]])   (train_classes == arange(C))

#define B_SZ 16384
#define D_SZ 256
#define C_SZ 2000
#define C_PAD 2048

// -------- device scratch (no allocs allowed) --------
__device__ __nv_bfloat16 g_predb[B_SZ * D_SZ];   // [B, D]  bf16, K-major (A operand)
__device__ __nv_bfloat16 g_sigT[C_PAD * D_SZ];   // [C_pad, D] bf16, K-major (B operand [N,K])
__device__ float g_gt[B_SZ];
__device__ float g_partials[2048];
__device__ unsigned int g_done;                  // zeroed by convA each launch

__device__ __forceinline__ uint32_t smem_u32(const void* p) {
    uint32_t a;
    asm("{ .reg .u64 t; cvta.to.shared.u64 t, %1; cvt.u32.u64 %0, t; }" : "=r"(a) : "l"(p));
    return a;
}

#define CP_ASYNC16(sm, gm) \
    asm volatile("cp.async.cg.shared.global [%0], [%1], 16;" :: "r"(sm), "l"(gm))
#define CP_COMMIT()  asm volatile("cp.async.commit_group;")
#define CP_WAIT(n)   asm volatile("cp.async.wait_group %0;" :: "n"(n) : "memory")

#define LDSM_X4(r0, r1, r2, r3, addr) \
    asm volatile("ldmatrix.sync.aligned.m8n8.x4.shared.b16 {%0,%1,%2,%3}, [%4];" \
                 : "=r"(r0), "=r"(r1), "=r"(r2), "=r"(r3) : "r"(addr))

#define MMA_BF16(c, a, b) \
    asm volatile("mma.sync.aligned.m16n8k16.row.col.f32.bf16.bf16.f32 " \
                 "{%0,%1,%2,%3}, {%4,%5,%6,%7}, {%8,%9}, {%0,%1,%2,%3};" \
                 : "+f"((c)[0]), "+f"((c)[1]), "+f"((c)[2]), "+f"((c)[3]) \
                 : "r"((a)[0]), "r"((a)[1]), "r"((a)[2]), "r"((a)[3]), \
                   "r"((b)[0]), "r"((b)[1]))

// ===================== conversion kernels =====================
__global__ void convA_kernel(const float4* __restrict__ pred) {
    int i = blockIdx.x * blockDim.x + threadIdx.x;      // B*D/4 float4s
    if (i == 0) g_done = 0;                             // reset completion counter
    float4 v = pred[i];
    __nv_bfloat162 lo = __float22bfloat162_rn(make_float2(v.x, v.y));
    __nv_bfloat162 hi = __float22bfloat162_rn(make_float2(v.z, v.w));
    uint2 o;
    o.x = *reinterpret_cast<unsigned int*>(&lo);
    o.y = *reinterpret_cast<unsigned int*>(&hi);
    reinterpret_cast<uint2*>(g_predb)[i] = o;
}

__global__ void convB_kernel(const float* __restrict__ sig, int C) {
    __shared__ float tile[32][33];
    int c0 = blockIdx.x * 32, d0 = blockIdx.y * 32;
    int tx = threadIdx.x, ty = threadIdx.y;             // block (32, 8)
    #pragma unroll
    for (int i = 0; i < 4; i++) {
        int d = d0 + ty + i * 8, c = c0 + tx;
        tile[ty + i * 8][tx] = (c < C) ? sig[d * C + c] : 0.f;
    }
    __syncthreads();
    #pragma unroll
    for (int i = 0; i < 4; i++) {
        int c = c0 + ty + i * 8, d = d0 + tx;           // c < 2048 always valid (padded)
        g_sigT[c * D_SZ + d] = __float2bfloat16(tile[tx][ty + i * 8]);
    }
}

// ===================== gt: contiguous row dots =====================
__global__ void gt_kernel(const int* __restrict__ label) {
    int row = blockIdx.x * 8 + (threadIdx.x >> 5);
    int lane = threadIdx.x & 31;
    int lab = label[row];
    float4 a4 = reinterpret_cast<const float4*>(g_predb)[row * 32 + lane];
    float4 b4 = reinterpret_cast<const float4*>(g_sigT)[lab * 32 + lane];
    const __nv_bfloat162* ap = reinterpret_cast<const __nv_bfloat162*>(&a4);
    const __nv_bfloat162* bp = reinterpret_cast<const __nv_bfloat162*>(&b4);
    float s = 0.f;
    #pragma unroll
    for (int i = 0; i < 4; i++) {
        float2 fa = __bfloat1622float2(ap[i]);
        float2 fb = __bfloat1622float2(bp[i]);
        s += fa.x * fb.x + fa.y * fb.y;
    }
    #pragma unroll
    for (int o = 16; o > 0; o >>= 1) s += __shfl_down_sync(0xffffffffu, s, o);
    if (lane == 0) g_gt[row] = s;
}

// ===================== HMMA GEMM + hinge =====================
// CTA tile 128x128, 8 warps (warp tile 32x64), BK=64.
// 3-stage cp.async pipeline with loads issued at the TOP of each iteration
// (stage freed two iterations ago) -> 2 chunks of load lead everywhere.
#define STAGE_BYTES 16384
#define SMEM_B_OFF  49152                       // 3 A stages
#define SMEM_TOTAL  98304                       // + 3 B stages

// swizzled offset within a stage: row r (0..127), 16B-segment seg (0..7)
__device__ __forceinline__ uint32_t swoff(int r, int seg) {
    return (uint32_t)(r * 128 + ((seg ^ (r & 7)) << 4));
}

__global__ void __launch_bounds__(256, 2)
gemm_hinge_kernel(const int* __restrict__ label, int C,
                  float* __restrict__ out, int nParts) {
    extern __shared__ char smem[];
    const uint32_t sb = smem_u32(smem);
    const int tid = threadIdx.x;
    const int wid = tid >> 5, lane = tid & 31;
    const int rowBase = blockIdx.y * 128;
    const int colBase = blockIdx.x * 128;

    // warp tile: 32 (M) x 64 (N)
    const int m0 = (wid & 3) * 32;
    const int n0 = (wid >> 2) * 64;

    const __nv_bfloat16* Agm = g_predb + (size_t)rowBase * D_SZ;
    const __nv_bfloat16* Bgm = g_sigT + (size_t)colBase * D_SZ;

#define LOAD_CHUNK(stage, chunk)                                              \
    do {                                                                      \
        _Pragma("unroll")                                                     \
        for (int it = 0; it < 4; it++) {                                      \
            int idx = it * 256 + tid;                                         \
            int r = idx >> 3, seg = idx & 7;                                  \
            CP_ASYNC16(sb + (stage) * STAGE_BYTES + swoff(r, seg),            \
                       Agm + (size_t)r * D_SZ + (chunk) * 64 + seg * 8);      \
            CP_ASYNC16(sb + SMEM_B_OFF + (stage) * STAGE_BYTES + swoff(r, seg), \
                       Bgm + (size_t)r * D_SZ + (chunk) * 64 + seg * 8);      \
        }                                                                     \
        CP_COMMIT();                                                          \
    } while (0)

    float acc[2][8][4];
    #pragma unroll
    for (int i = 0; i < 2; i++)
        #pragma unroll
        for (int j = 0; j < 8; j++)
            #pragma unroll
            for (int q = 0; q < 4; q++) acc[i][j][q] = 0.f;

    // prologue: chunks 0,1 -> stages 0,1
    LOAD_CHUNK(0, 0);
    LOAD_CHUNK(1, 1);

    // ldmatrix per-lane address components
    const int rA = m0 + (lane & 15);            // + am*16
    const int rA7 = rA & 7;
    const int aSegHalf = (lane >> 4);           // 0/1 -> k half
    const int nB = n0 + ((lane >> 4) << 3) + (lane & 7);   // + bp*16
    const int nB7 = nB & 7;
    const int bSegHalf = (lane >> 3) & 1;

#define COMPUTE_CHUNK(stage)                                                  \
    do {                                                                      \
        const uint32_t Abase = sb + (stage) * STAGE_BYTES;                    \
        const uint32_t Bbase = sb + SMEM_B_OFF + (stage) * STAGE_BYTES;       \
        _Pragma("unroll")                                                     \
        for (int s = 0; s < 4; s++) {                                         \
            uint32_t a[2][4];                                                 \
            _Pragma("unroll")                                                 \
            for (int am = 0; am < 2; am++) {                                  \
                int r = rA + am * 16;                                         \
                uint32_t addr = Abase + r * 128 +                             \
                                (((s * 2 + aSegHalf) ^ rA7) << 4);            \
                LDSM_X4(a[am][0], a[am][1], a[am][2], a[am][3], addr);        \
            }                                                                 \
            uint32_t b[8][2];                                                 \
            _Pragma("unroll")                                                 \
            for (int bp = 0; bp < 4; bp++) {                                  \
                int n = nB + bp * 16;                                         \
                uint32_t addr = Bbase + n * 128 +                             \
                                (((s * 2 + bSegHalf) ^ nB7) << 4);            \
                uint32_t r0, r1, r2, r3;                                      \
                LDSM_X4(r0, r1, r2, r3, addr);                                \
                b[bp * 2][0] = r0; b[bp * 2][1] = r1;                         \
                b[bp * 2 + 1][0] = r2; b[bp * 2 + 1][1] = r3;                 \
            }                                                                 \
            _Pragma("unroll")                                                 \
            for (int am = 0; am < 2; am++)                                    \
                _Pragma("unroll")                                             \
                for (int an = 0; an < 8; an++)                                \
                    MMA_BF16(acc[am][an], a[am], b[an]);                      \
        }                                                                     \
    } while (0)

    // kc=0: wait c0 (outstanding {0,1} -> <=1), sync, load c2->s2, compute s0
    CP_WAIT(1); __syncthreads();
    LOAD_CHUNK(2, 2);
    COMPUTE_CHUNK(0);

    // kc=1: wait c1 ({1,2} -> <=1), sync (s0 compute done by all), load c3->s0, compute s1
    CP_WAIT(1); __syncthreads();
    LOAD_CHUNK(0, 3);
    COMPUTE_CHUNK(1);

    // kc=2: wait c2 ({2,3} -> <=1), sync, compute s2
    CP_WAIT(1); __syncthreads();
    COMPUTE_CHUNK(2);

    // kc=3: wait c3, sync, compute s0
    CP_WAIT(0); __syncthreads();
    COMPUTE_CHUNK(0);

    // --- hinge epilogue ---
    const int groupID = lane >> 2, tig = lane & 3;
    float lsum = 0.f;
    #pragma unroll
    for (int am = 0; am < 2; am++) {
        int r0g = rowBase + m0 + am * 16 + groupID;
        int r1g = r0g + 8;
        float gt0 = g_gt[r0g], gt1 = g_gt[r1g];
        int lab0 = label[r0g], lab1 = label[r1g];
        #pragma unroll
        for (int an = 0; an < 8; an++) {
            int c0 = colBase + n0 + an * 8 + 2 * tig;
            int c1 = c0 + 1;
            float* v = acc[am][an];
            if (c0 < C && c0 != lab0) lsum += fmaxf(1.0f + v[0] - gt0, 0.f);
            if (c1 < C && c1 != lab0) lsum += fmaxf(1.0f + v[1] - gt0, 0.f);
            if (c0 < C && c0 != lab1) lsum += fmaxf(1.0f + v[2] - gt1, 0.f);
            if (c1 < C && c1 != lab1) lsum += fmaxf(1.0f + v[3] - gt1, 0.f);
        }
    }

    // deterministic block tree reduction (reuse smem)
    float* red = reinterpret_cast<float*>(smem);
    __syncthreads();
    red[tid] = lsum;
    __syncthreads();
    #pragma unroll
    for (int st = 128; st > 0; st >>= 1) {
        if (tid < st) red[tid] += red[tid + st];
        __syncthreads();
    }

    // last CTA does the (deterministic, fixed-order) final reduction
    __shared__ unsigned int s_rank;
    if (tid == 0) {
        g_partials[blockIdx.y * gridDim.x + blockIdx.x] = red[0];
        __threadfence();
        s_rank = atomicAdd(&g_done, 1u);
    }
    __syncthreads();
    if (s_rank == (unsigned)(nParts - 1)) {
        float v = 0.f;
        for (int i = tid; i < nParts; i += 256) v += g_partials[i];
        __syncthreads();
        red[tid] = v;
        __syncthreads();
        #pragma unroll
        for (int st = 128; st > 0; st >>= 1) {
            if (tid < st) red[tid] += red[tid + st];
            __syncthreads();
        }
        if (tid == 0) out[0] = red[0];
    }
}

extern "C" void kernel_launch(void* const* d_in, const int* in_sizes, int n_in,
                              void* d_out, int out_size) {
    const float* pred  = (const float*)d_in[0];   // [B, D] fp32
    const int*   label = (const int*)d_in[1];     // [B] int32
    const float* sig   = (const float*)d_in[3];   // [D, C] fp32
    const int C = in_sizes[2];                    // 2000

    convA_kernel<<<4096, 256>>>(reinterpret_cast<const float4*>(pred));
    convB_kernel<<<dim3(64, 8), dim3(32, 8)>>>(sig, C);
    gt_kernel<<<B_SZ / 8, 256>>>(label);

    cudaFuncSetAttribute(gemm_hinge_kernel,
                         cudaFuncAttributeMaxDynamicSharedMemorySize, SMEM_TOTAL);
    dim3 grid(C_PAD / 128, B_SZ / 128);           // (16, 128) = 2048 CTAs
    gemm_hinge_kernel<<<grid, 256, SMEM_TOTAL>>>(label, C, (float*)d_out,
                                                 grid.x * grid.y);
}

// round 9
// speedup vs baseline: 2.1330x; 2.1330x over previous
#include <cuda_runtime.h>
#include <cuda_bf16.h>
#include <cstdint>

// Shapes fixed by dataset: B=16384, D=256, C=2000.
// loss = sum_{b, c != label[b]} max(1 + (pred@sig)[b,c] - gt[b], 0)
// gt[b] = dot(pred[b,:], sig[:,label[b]])   (train_classes == arange(C))

#define B_SZ 16384
#define D_SZ 256
#define C_SZ 2000
#define C_PAD 2048

// -------- device scratch (no allocs allowed) --------
__device__ __nv_bfloat16 g_predb[B_SZ * D_SZ];   // [B, D]  bf16, K-major (A operand)
__device__ __nv_bfloat16 g_sigT[C_PAD * D_SZ];   // [C_pad, D] bf16, K-major (B operand [N,K])
__device__ float g_gt[B_SZ];
__device__ float g_partials[2048];

__device__ __forceinline__ uint32_t smem_u32(const void* p) {
    uint32_t a;
    asm("{ .reg .u64 t; cvta.to.shared.u64 t, %1; cvt.u32.u64 %0, t; }" : "=r"(a) : "l"(p));
    return a;
}

#define CP_ASYNC16(sm, gm) \
    asm volatile("cp.async.cg.shared.global [%0], [%1], 16;" :: "r"(sm), "l"(gm))
#define CP_COMMIT() asm volatile("cp.async.commit_group;")
#define CP_WAIT1()  asm volatile("cp.async.wait_group 1;" ::: "memory")

#define LDSM_X4(r0, r1, r2, r3, addr) \
    asm volatile("ldmatrix.sync.aligned.m8n8.x4.shared.b16 {%0,%1,%2,%3}, [%4];" \
                 : "=r"(r0), "=r"(r1), "=r"(r2), "=r"(r3) : "r"(addr))

#define MMA_BF16(c, a, b) \
    asm volatile("mma.sync.aligned.m16n8k16.row.col.f32.bf16.bf16.f32 " \
                 "{%0,%1,%2,%3}, {%4,%5,%6,%7}, {%8,%9}, {%0,%1,%2,%3};" \
                 : "+f"((c)[0]), "+f"((c)[1]), "+f"((c)[2]), "+f"((c)[3]) \
                 : "r"((a)[0]), "r"((a)[1]), "r"((a)[2]), "r"((a)[3]), \
                   "r"((b)[0]), "r"((b)[1]))

// ===================== convB: sig [D,C] -> sigT [C_pad, D] bf16 =====================
__global__ void convB_kernel(const float* __restrict__ sig, int C) {
    __shared__ float tile[32][33];
    int c0 = blockIdx.x * 32, d0 = blockIdx.y * 32;
    int tx = threadIdx.x, ty = threadIdx.y;             // block (32, 8)
    #pragma unroll
    for (int i = 0; i < 4; i++) {
        int d = d0 + ty + i * 8, c = c0 + tx;
        tile[ty + i * 8][tx] = (c < C) ? sig[d * C + c] : 0.f;
    }
    __syncthreads();
    #pragma unroll
    for (int i = 0; i < 4; i++) {
        int c = c0 + ty + i * 8, d = d0 + tx;           // c < 2048 always valid (padded)
        g_sigT[c * D_SZ + d] = __float2bfloat16(tile[tx][ty + i * 8]);
    }
}

// ===================== fused convA + gt =====================
// One warp per pred row: convert fp32->bf16 (store to g_predb) and compute
// gt[row] = dot(pred_row_fp32, sigT[label[row]]) in the same pass.
__global__ void convA_gt_kernel(const float* __restrict__ pred,
                                const int* __restrict__ label) {
    int row  = blockIdx.x * 8 + (threadIdx.x >> 5);
    int lane = threadIdx.x & 31;
    int lab  = label[row];

    // lane covers cols [lane*8, lane*8+8)
    const float4* src = reinterpret_cast<const float4*>(pred + (size_t)row * D_SZ) + lane * 2;
    float4 v0 = src[0];
    float4 v1 = src[1];

    // bf16 pack -> g_predb
    __nv_bfloat162 p0 = __float22bfloat162_rn(make_float2(v0.x, v0.y));
    __nv_bfloat162 p1 = __float22bfloat162_rn(make_float2(v0.z, v0.w));
    __nv_bfloat162 p2 = __float22bfloat162_rn(make_float2(v1.x, v1.y));
    __nv_bfloat162 p3 = __float22bfloat162_rn(make_float2(v1.z, v1.w));
    uint4 o;
    o.x = *reinterpret_cast<unsigned int*>(&p0);
    o.y = *reinterpret_cast<unsigned int*>(&p1);
    o.z = *reinterpret_cast<unsigned int*>(&p2);
    o.w = *reinterpret_cast<unsigned int*>(&p3);
    reinterpret_cast<uint4*>(g_predb + (size_t)row * D_SZ)[lane] = o;

    // gt partial: fp32 pred x (bf16->fp32) sigT[lab]
    float4 b4 = reinterpret_cast<const float4*>(g_sigT + (size_t)lab * D_SZ)[lane];
    const __nv_bfloat162* bp = reinterpret_cast<const __nv_bfloat162*>(&b4);
    float2 s0 = __bfloat1622float2(bp[0]);
    float2 s1 = __bfloat1622float2(bp[1]);
    float2 s2 = __bfloat1622float2(bp[2]);
    float2 s3 = __bfloat1622float2(bp[3]);
    float s = v0.x * s0.x + v0.y * s0.y + v0.z * s1.x + v0.w * s1.y
            + v1.x * s2.x + v1.y * s2.y + v1.z * s3.x + v1.w * s3.y;
    #pragma unroll
    for (int off = 16; off > 0; off >>= 1) s += __shfl_down_sync(0xffffffffu, s, off);
    if (lane == 0) g_gt[row] = s;
}

// ===================== HMMA GEMM + hinge (R4 mainloop, verbatim) =====================
// CTA tile 128x128, 8 warps (warp tile 32x64), BK=64, double-buffered cp.async.
#define STAGE_BYTES 16384
#define SMEM_B_OFF  32768
#define SMEM_TOTAL  65536

// swizzled offset within a stage: row r (0..127), 16B-segment seg (0..7)
__device__ __forceinline__ uint32_t swoff(int r, int seg) {
    return (uint32_t)(r * 128 + ((seg ^ (r & 7)) << 4));
}

__global__ void __launch_bounds__(256, 2)
gemm_hinge_kernel(const int* __restrict__ label, int C) {
    extern __shared__ char smem[];
    const uint32_t sb = smem_u32(smem);
    const int tid = threadIdx.x;
    const int wid = tid >> 5, lane = tid & 31;
    const int rowBase = blockIdx.y * 128;
    const int colBase = blockIdx.x * 128;

    // warp tile: 32 (M) x 64 (N)
    const int m0 = (wid & 3) * 32;
    const int n0 = (wid >> 2) * 64;

    const __nv_bfloat16* Agm = g_predb + (size_t)rowBase * D_SZ;
    const __nv_bfloat16* Bgm = g_sigT + (size_t)colBase * D_SZ;

    float acc[2][8][4];
    #pragma unroll
    for (int i = 0; i < 2; i++)
        #pragma unroll
        for (int j = 0; j < 8; j++)
            #pragma unroll
            for (int q = 0; q < 4; q++) acc[i][j][q] = 0.f;

    // prefetch chunks 0,1
    #pragma unroll
    for (int st = 0; st < 2; st++) {
        #pragma unroll
        for (int it = 0; it < 4; it++) {
            int idx = it * 256 + tid;
            int r = idx >> 3, seg = idx & 7;
            CP_ASYNC16(sb + st * STAGE_BYTES + swoff(r, seg),
                       Agm + (size_t)r * D_SZ + st * 64 + seg * 8);
            CP_ASYNC16(sb + SMEM_B_OFF + st * STAGE_BYTES + swoff(r, seg),
                       Bgm + (size_t)r * D_SZ + st * 64 + seg * 8);
        }
        CP_COMMIT();
    }

    // ldmatrix per-lane address components
    const int rA = m0 + (lane & 15);           // + am*16
    const int rA7 = rA & 7;
    const int aSegHalf = (lane >> 4);          // 0/1 -> k half
    const int nB = n0 + ((lane >> 4) << 3) + (lane & 7);   // + bp*16
    const int nB7 = nB & 7;
    const int bSegHalf = (lane >> 3) & 1;

    for (int kc = 0; kc < 4; kc++) {
        CP_WAIT1();
        __syncthreads();
        const uint32_t Abase = sb + (kc & 1) * STAGE_BYTES;
        const uint32_t Bbase = sb + SMEM_B_OFF + (kc & 1) * STAGE_BYTES;

        #pragma unroll
        for (int s = 0; s < 4; s++) {
            uint32_t a[2][4];
            #pragma unroll
            for (int am = 0; am < 2; am++) {
                int r = rA + am * 16;
                uint32_t addr = Abase + r * 128 +
                                (((s * 2 + aSegHalf) ^ rA7) << 4);
                LDSM_X4(a[am][0], a[am][1], a[am][2], a[am][3], addr);
            }
            uint32_t b[8][2];
            #pragma unroll
            for (int bp = 0; bp < 4; bp++) {           // 2 n-atoms per ldmatrix.x4
                int n = nB + bp * 16;
                uint32_t addr = Bbase + n * 128 +
                                (((s * 2 + bSegHalf) ^ nB7) << 4);
                uint32_t r0, r1, r2, r3;
                LDSM_X4(r0, r1, r2, r3, addr);
                b[bp * 2][0] = r0; b[bp * 2][1] = r1;
                b[bp * 2 + 1][0] = r2; b[bp * 2 + 1][1] = r3;
            }
            #pragma unroll
            for (int am = 0; am < 2; am++)
                #pragma unroll
                for (int an = 0; an < 8; an++)
                    MMA_BF16(acc[am][an], a[am], b[an]);
        }
        __syncthreads();
        if (kc < 2) {
            int nc = kc + 2;
            #pragma unroll
            for (int it = 0; it < 4; it++) {
                int idx = it * 256 + tid;
                int r = idx >> 3, seg = idx & 7;
                CP_ASYNC16(sb + (kc & 1) * STAGE_BYTES + swoff(r, seg),
                           Agm + (size_t)r * D_SZ + nc * 64 + seg * 8);
                CP_ASYNC16(sb + SMEM_B_OFF + (kc & 1) * STAGE_BYTES + swoff(r, seg),
                           Bgm + (size_t)r * D_SZ + nc * 64 + seg * 8);
            }
        }
        CP_COMMIT();
    }

    // --- hinge epilogue ---
    // accum mapping (m16n8): c0,c1 -> row groupID, cols 2*tig, 2*tig+1
    //                        c2,c3 -> row groupID+8, same cols
    const int groupID = lane >> 2, tig = lane & 3;
    float lsum = 0.f;
    #pragma unroll
    for (int am = 0; am < 2; am++) {
        int r0g = rowBase + m0 + am * 16 + groupID;
        int r1g = r0g + 8;
        float gt0 = g_gt[r0g], gt1 = g_gt[r1g];
        int lab0 = label[r0g], lab1 = label[r1g];
        #pragma unroll
        for (int an = 0; an < 8; an++) {
            int c0 = colBase + n0 + an * 8 + 2 * tig;
            int c1 = c0 + 1;
            float* v = acc[am][an];
            if (c0 < C && c0 != lab0) lsum += fmaxf(1.0f + v[0] - gt0, 0.f);
            if (c1 < C && c1 != lab0) lsum += fmaxf(1.0f + v[1] - gt0, 0.f);
            if (c0 < C && c0 != lab1) lsum += fmaxf(1.0f + v[2] - gt1, 0.f);
            if (c1 < C && c1 != lab1) lsum += fmaxf(1.0f + v[3] - gt1, 0.f);
        }
    }

    // deterministic reduction: warp shuffle + single smem stage
    #pragma unroll
    for (int off = 16; off > 0; off >>= 1)
        lsum += __shfl_down_sync(0xffffffffu, lsum, off);
    __shared__ float wsum[8];
    if (lane == 0) wsum[wid] = lsum;
    __syncthreads();
    if (tid == 0) {
        float t = 0.f;
        #pragma unroll
        for (int i = 0; i < 8; i++) t += wsum[i];
        g_partials[blockIdx.y * gridDim.x + blockIdx.x] = t;
    }
}

// ===================== deterministic final reduction =====================
__global__ void final_reduce_kernel(float* __restrict__ out, int n) {
    __shared__ float s[256];
    float v = 0.f;
    for (int i = threadIdx.x; i < n; i += 256) v += g_partials[i];
    s[threadIdx.x] = v;
    __syncthreads();
    #pragma unroll
    for (int st = 128; st > 0; st >>= 1) {
        if (threadIdx.x < st) s[threadIdx.x] += s[threadIdx.x + st];
        __syncthreads();
    }
    if (threadIdx.x == 0) out[0] = s[0];
}

extern "C" void kernel_launch(void* const* d_in, const int* in_sizes, int n_in,
                              void* d_out, int out_size) {
    const float* pred  = (const float*)d_in[0];   // [B, D] fp32
    const int*   label = (const int*)d_in[1];     // [B] int32
    const float* sig   = (const float*)d_in[3];   // [D, C] fp32
    const int C = in_sizes[2];                    // 2000

    convB_kernel<<<dim3(64, 8), dim3(32, 8)>>>(sig, C);
    convA_gt_kernel<<<B_SZ / 8, 256>>>(pred, label);

    cudaFuncSetAttribute(gemm_hinge_kernel,
                         cudaFuncAttributeMaxDynamicSharedMemorySize, SMEM_TOTAL);
    dim3 grid(C_PAD / 128, B_SZ / 128);           // (16, 128) = 2048 CTAs
    gemm_hinge_kernel<<<grid, 256, SMEM_TOTAL>>>(label, C);

    final_reduce_kernel<<<1, 256>>>((float*)d_out, grid.x * grid.y);
}